// round 16
// baseline (speedup 1.0000x reference)
#include <cuda_runtime.h>

#define FULL 0xffffffffu

constexpr int B = 4096;
constexpr int K = 64;
constexpr int L = 128;
constexpr int E_DIM = 16;

__device__ float g_loss[B];
__device__ unsigned g_ctr = 0;

// Wavefront-pipelined pHMM forward, ONE batch element per 32-lane warp,
// TWO states per lane: lane j owns states {2j, 2j+1}; lane 31 shadows
// state 64. At wall-iteration w lane j processes step l = w - j, consuming
// lane j-1's same-step exports (nv1 = fM'[2j], nfd2 = fD'[2j]) produced at
// iteration w-1. 159 iterations total (skew 31 + 128 steps).
//
// Flowing initialization (no ramp guards): all-zero state is an exact
// fixpoint; lane 0 is preset (fM[0]=1, fD[1]=Amd0, exports fDinit[2]) and
// the init delete-chain flows down the wavefront like a regular step.
//
// SI fold: SI_k = Adm-side premultiplied insert state (Aim_k * fI_k), so
// q_k = Amm*FM + Adm*FD + SI. SI'_k = P_k*FM_k + AqII_k*SI_k,
// P_k = Aim_k * 0.25 * exp(M2I), AqII_k = 0.25 * exp(I2I). State 64:
// SI64 = A64im * fI64, used directly in the final sum.
//
// Per-lane power-of-2 exponent Ex; alignment af = 2^(E_{j-1}-E_j) is
// piecewise-constant between rescale heads ((w & 3) == 3), refreshed there;
// af = 0 on lane 0. Rescale max includes the SI values (self-loop, R11
// failure mode) and all state. Idle lanes force exv = 0.
// Import pipelining: next iteration's shuffles + emission LDS.64 issue
// after commit. Transitions order: M2M,M2I,M2D,I2M,I2I,D2M,D2D.

#define ITER(WV, RESC) do {                                                    \
    /* imports pv1in/pfdin/evcur prefetched by the previous iteration */       \
    float pv1a = pv1in * af;                                                   \
    float pfda = pfdin * af;                                                   \
    float q0 = fmaf(Amm0, FM0, fmaf(Adm0, FD0, SI0));                          \
    float q1 = fmaf(Amm1, FM1, fmaf(Adm1, FD1, SI1));                          \
    float nI0 = fmaf(P0, FM0, AqII0 * SI0);                                    \
    float nI1 = fmaf(P1, FM1, AqII1 * SI1);                                    \
    float nSI64 = fmaf(P64, v1x, Aq64II * SI64);                               \
    float v0  = evcur.x * q0;                                                  \
    float nv1 = evcur.y * q1;                                                  \
    float u0 = Amd0_ * pv1a, u1 = Amd1_ * v0;                                  \
    float alpha = fmaf(Add1, u0, u1);                                          \
    float fd0 = pfda;                                                          \
    float nfd2 = fmaf(segB, fd0, alpha);     /* export: 1 FMA off import */    \
    float fd1 = fmaf(Add0, fd0, u0);                                           \
    float nM0 = pv1a, nM1 = v0;                                                \
    int exv = 0;                                                               \
    if (RESC) {                                                                \
        float m = fmaxf(fmaxf(nM0, nM1), fmaxf(nI0, nI1));                     \
        m = fmaxf(m, fmaxf(fd0, fd1));                                         \
        m = fmaxf(m, fmaxf(nv1, fmaxf(nfd2, nSI64)));                          \
        exv = (int)((__float_as_uint(m) >> 23) & 255) - 127;                   \
        exv = (m > 0.0f) ? exv : 0;          /* idle lanes: no-op rescale */   \
        float sc = __uint_as_float((unsigned)(127 - exv) << 23);               \
        nM0 *= sc; nM1 *= sc; nI0 *= sc; nI1 *= sc;                            \
        fd0 *= sc; fd1 *= sc;                                                  \
        nv1 *= sc; nfd2 *= sc; nSI64 *= sc;                                    \
    }                                                                          \
    FM0 = nM0; FM1 = nM1; SI0 = nI0; SI1 = nI1;                                \
    FD0 = fd0; FD1 = fd1;                                                      \
    SI64 = nSI64; v1x = nv1; fd2x = nfd2; Ex += exv;                           \
    if (RESC) {   /* refresh alignment factor (valid until next head) */       \
        int pE = __shfl_up_sync(FULL, Ex, 1);                                  \
        int dE = pE - Ex; dE = max(-126, min(126, dE));                        \
        af = (j == 0) ? 0.0f                                                   \
                      : __uint_as_float((unsigned)(127 + dE) << 23);           \
    }                                                                          \
    /* prefetch imports + emission pair for iteration WV+1 */                  \
    pv1in = __shfl_up_sync(FULL, v1x, 1);                                      \
    pfdin = __shfl_up_sync(FULL, fd2x, 1);                                     \
    evcur = *(const float2*)(epbh + rawp[WV]);  /* symbol of step WV+1-j */    \
} while (0)

__global__ __launch_bounds__(64) void phmm_kernel(
    const int*   __restrict__ x,
    const float* __restrict__ a,
    const float* __restrict__ e,
    const float* __restrict__ mus,
    const float* __restrict__ lvs,
    float*       __restrict__ out)
{
    const int j    = threadIdx.x & 31;       // lane
    const int wIn  = threadIdx.x >> 5;
    const int b    = blockIdx.x * 2 + wIn;   // one batch element per warp

    __shared__ float2 sh_e[2 * 4 * 32];      // [warp][symbol][lane]
    __shared__ int    sh_x[2 * 224];         // padded symbols (×256 pre-scaled)
    __shared__ float  sw[2];
    __shared__ unsigned s_rank;

    const float* ab = a + (size_t)b * (K + 1) * 7;
    const int k0 = 2 * j;
    const float* A0 = ab + (k0 + 0) * 7;
    const float* A1 = ab + (k0 + 1) * 7;

    float Amm0 = __expf(A0[0]), Amm1 = __expf(A1[0]);
    float Amd0_ = __expf(A0[2]), Amd1_ = __expf(A1[2]);   // M2D
    float Aim0 = __expf(A0[3]), Aim1 = __expf(A1[3]);
    float P0 = Aim0 * 0.25f * __expf(A0[1]);
    float P1 = Aim1 * 0.25f * __expf(A1[1]);
    float AqII0 = 0.25f * __expf(A0[4]), AqII1 = 0.25f * __expf(A1[4]);
    float Adm0 = __expf(A0[5]), Adm1 = __expf(A1[5]);     // D2M
    float Add0 = __expf(A0[6]), Add1 = __expf(A1[6]);     // D2D
    float segB = Add0 * Add1;

    const float* a64 = ab + K * 7;
    float A64mm  = __expf(a64[0]);
    float A64im  = __expf(a64[3]);
    float P64    = A64im * 0.25f * __expf(a64[1]);
    float Aq64II = 0.25f * __expf(a64[4]);
    float A64dm  = __expf(a64[5]);

    // Emission LUT (conflict-free LDS.64): epb[sym*32+j] = {exp(e[2j][sym]), exp(e[2j+1][sym])}
    const float4* e4 = (const float4*)(e + (size_t)b * K * 4);
    float4 e0 = e4[k0], e1 = e4[k0 + 1];
    float2* epb = sh_e + (size_t)wIn * 4 * 32;
    epb[0 * 32 + j] = make_float2(__expf(e0.x), __expf(e1.x));
    epb[1 * 32 + j] = make_float2(__expf(e0.y), __expf(e1.y));
    epb[2 * 32 + j] = make_float2(__expf(e0.z), __expf(e1.z));
    epb[3 * 32 + j] = make_float2(__expf(e0.w), __expf(e1.w));
    const char* epbh = (const char*)epb + j * 8;

    // Symbols to shared, pre-scaled by 256 (LUT row = 32 * 8B = 256B),
    // padded 32 front / 32 back so the skewed prefetch never clamps.
    const int4* x4 = (const int4*)(x + (size_t)b * L);
    int* xr = sh_x + wIn * 224;
    {
        int4 xa = x4[j & 31];
        xr[j] = 0; xr[192 + j] = 0;          // front pad [0,32), back pad [192,224)
        xr[32 + 4 * j + 0] = xa.x << 8;      // symbols at [32, 160)
        xr[32 + 4 * j + 1] = xa.y << 8;
        xr[32 + 4 * j + 2] = xa.z << 8;
        xr[32 + 4 * j + 3] = xa.w << 8;
    }
    // lane j holds x[4j..4j+3] via one int4; need 128 ints = 32 lanes × 4 ✓
    const int* rawp = xr + 33 - j;           // rawp[w] = x[w - j + 1] << 8

    // Flowing init: lane 0 preset; all other lanes exactly zero.
    float FM0 = (j == 0) ? 1.0f : 0.0f;
    float FM1 = 0.0f;
    float SI0 = 0.0f, SI1 = 0.0f, SI64 = 0.0f;
    float FD0 = 0.0f, FD1 = 0.0f;
    float v1x = 0.0f;                 // export fM'[2j+2] / fM[64] shadow
    float fd2x = 0.0f;                // export fD'[2j+2] / fD[64] shadow
    if (j == 0) {
        FD1 = Amd0_;                  // fDinit[1] = Amd[0] * fM0[0]
        fd2x = Add1 * FD1;            // export fDinit[2] for lane 1's init step
    }
    int Ex = 0;
    float af = (j == 0) ? 0.0f : 1.0f;

    __syncthreads();                  // shared LUTs + symbols visible

    // Prologue prefetch for iteration 0: symbol index rawp[-1] = xr[32 - j]
    // (x[0] for lane 0, pad 0 otherwise).
    float pv1in = __shfl_up_sync(FULL, v1x, 1);
    float pfdin = __shfl_up_sync(FULL, fd2x, 1);
    float2 evcur = *(const float2*)(epbh + xr[32 - j]);

    // ── uniform, guard-free loop: w = 0..158; rescale heads at w ≡ 3 (mod 4)
    ITER(0, false);
    ITER(1, false);
    ITER(2, false);
    #pragma unroll 1
    for (int wb = 3; wb < 159; wb += 4) {
        ITER(wb,     true);
        ITER(wb + 1, false);
        ITER(wb + 2, false);
        ITER(wb + 3, false);
    }

    // KLD: lanes 0..15 handle the 16 latent dims.
    float kt = 0.0f;
    if (j < E_DIM) {
        float mu = mus[(size_t)b * E_DIM + j];
        float lv = lvs[(size_t)b * E_DIM + j];
        kt = 1.0f + lv - mu * mu - __expf(lv);
    }
    kt += __shfl_xor_sync(FULL, kt, 16);
    kt += __shfl_xor_sync(FULL, kt, 8);
    kt += __shfl_xor_sync(FULL, kt, 4);
    kt += __shfl_xor_sync(FULL, kt, 2);
    kt += __shfl_xor_sync(FULL, kt, 1);
    float kld = -0.5f * kt;

    if (j == 31) {
        // Lane 31's step 127 committed at w = 158:
        // fM[64]=v1x, A64im*fI[64]=SI64, fD[64]=fd2x at scale 2^Ex.
        float fin = fmaf(A64mm, v1x, fmaf(A64dm, fd2x, SI64));
        g_loss[b] = -(logf(fin) + (float)Ex * 0.69314718055994531f) + kld;
    }

    // ── Fused deterministic final reduction (last-block-done) ──
    __threadfence();
    __syncthreads();
    if (threadIdx.x == 0) s_rank = atomicAdd(&g_ctr, 1);
    __syncthreads();
    if (s_rank == gridDim.x - 1) {
        __threadfence();
        float v = 0.0f;
        #pragma unroll
        for (int i = 0; i < B / 64; ++i)
            v += __ldcg(&g_loss[threadIdx.x + i * 64]);
        v += __shfl_xor_sync(FULL, v, 16);
        v += __shfl_xor_sync(FULL, v, 8);
        v += __shfl_xor_sync(FULL, v, 4);
        v += __shfl_xor_sync(FULL, v, 2);
        v += __shfl_xor_sync(FULL, v, 1);
        if (j == 0) sw[wIn] = v;
        __syncthreads();
        if (threadIdx.x == 0) {
            out[0] = (sw[0] + sw[1]) * (1.0f / (float)B);
            g_ctr = 0;   // reset for next graph replay
        }
    }
}

extern "C" void kernel_launch(void* const* d_in, const int* in_sizes, int n_in,
                              void* d_out, int out_size)
{
    const int*   x   = (const int*)d_in[0];
    const float* a   = (const float*)d_in[1];
    const float* e   = (const float*)d_in[2];
    const float* mus = (const float*)d_in[3];
    const float* lvs = (const float*)d_in[4];

    // 2048 blocks × 2 warps, one batch element per warp = 4096.
    phmm_kernel<<<B / 2, 64>>>(x, a, e, mus, lvs, (float*)d_out);
}